// round 1
// baseline (speedup 1.0000x reference)
#include <cuda_runtime.h>
#include <cuda_bf16.h>

// ---------------------------------------------------------------------------
// VideoAttentionModel: B=8, S=4096, D=256, fp32.
//   q,k,v = x@W + b ; flash-attention ; logits = ctx@Wo + bo ;
//   w = logits@cv ; nw = softmax_seq(w) ; out = logits * nw
// Round 1: fp32 baseline using packed fma.rn.f32x2 (2x FFMA rate on sm_103a).
// ---------------------------------------------------------------------------

#define NROWS   32768           // B*S
#define DMODEL  256
#define NELEM   (NROWS * DMODEL)

typedef unsigned long long f2u;  // packed f32x2 in a 64-bit reg

__device__ __forceinline__ f2u dup2(float x) {
    f2u r; asm("mov.b64 %0, {%1, %1};" : "=l"(r) : "f"(x)); return r;
}
__device__ __forceinline__ void upk2(float &x, float &y, f2u v) {
    asm("mov.b64 {%0, %1}, %2;" : "=f"(x), "=f"(y) : "l"(v));
}
__device__ __forceinline__ void ffma2(f2u &d, f2u a, f2u b) {
    asm("fma.rn.f32x2 %0, %1, %2, %0;" : "+l"(d) : "l"(a), "l"(b));
}
__device__ __forceinline__ void fmul2(f2u &d, f2u a) {
    asm("mul.rn.f32x2 %0, %0, %1;" : "+l"(d) : "l"(a));
}

// Scratch (device globals: allocation-free rule)
__device__ float g_q[NELEM];
__device__ float g_k[NELEM];
__device__ float g_v[NELEM];
__device__ float g_ctx[NELEM];
__device__ float g_logits[NELEM];
__device__ float g_w[NROWS];

// ---------------------------------------------------------------------------
// SGEMM + bias: C[M,256] = A[M,256] @ B[256,256] + bias.  64x64 tile, BK=32.
// 256 threads, each owns 4x4 outputs; inner loop is f32x2.
// ---------------------------------------------------------------------------
__global__ __launch_bounds__(256) void sgemm_bias256(
    const float* __restrict__ A, const float* __restrict__ B,
    const float* __restrict__ bias, float* __restrict__ C)
{
    __shared__ float As[32][64];   // transposed: As[k][m]
    __shared__ float Bs[32][64];   // Bs[k][n]
    const int tid = threadIdx.x;
    const int tx = tid & 15, ty = tid >> 4;
    const int bm = blockIdx.y * 64, bn = blockIdx.x * 64;

    f2u acc[4][2] = {};
    for (int k0 = 0; k0 < 256; k0 += 32) {
#pragma unroll
        for (int i = 0; i < 2; i++) {
            int fi = tid + i * 256;
            int m = fi & 63, kq = fi >> 6;                       // A: 64 rows x 8 float4 of k
            float4 av = *(const float4*)(A + (size_t)(bm + m) * 256 + k0 + kq * 4);
            As[kq * 4 + 0][m] = av.x; As[kq * 4 + 1][m] = av.y;
            As[kq * 4 + 2][m] = av.z; As[kq * 4 + 3][m] = av.w;
            int n4 = fi & 15, kk = fi >> 4;                      // B: 32 rows x 16 float4 of n
            *(float4*)&Bs[kk][n4 * 4] =
                *(const float4*)(B + (size_t)(k0 + kk) * 256 + bn + n4 * 4);
        }
        __syncthreads();
#pragma unroll
        for (int k = 0; k < 32; k++) {
            float4 a = *(const float4*)&As[k][ty * 4];
            f2u b0 = *(const f2u*)&Bs[k][tx * 4];
            f2u b1 = *(const f2u*)&Bs[k][tx * 4 + 2];
            f2u t;
            t = dup2(a.x); ffma2(acc[0][0], t, b0); ffma2(acc[0][1], t, b1);
            t = dup2(a.y); ffma2(acc[1][0], t, b0); ffma2(acc[1][1], t, b1);
            t = dup2(a.z); ffma2(acc[2][0], t, b0); ffma2(acc[2][1], t, b1);
            t = dup2(a.w); ffma2(acc[3][0], t, b0); ffma2(acc[3][1], t, b1);
        }
        __syncthreads();
    }
    float4 bv = *(const float4*)(bias + bn + tx * 4);
#pragma unroll
    for (int j = 0; j < 4; j++) {
        float x0, x1, x2, x3;
        upk2(x0, x1, acc[j][0]); upk2(x2, x3, acc[j][1]);
        float4 o = make_float4(x0 + bv.x, x1 + bv.y, x2 + bv.z, x3 + bv.w);
        *(float4*)(C + (size_t)(bm + ty * 4 + j) * 256 + bn + tx * 4) = o;
    }
}

// ---------------------------------------------------------------------------
// Flash attention (fp32, non-causal). One block per (batch, 64-row q tile).
// smem: Qs[256][64] (transposed, pre-scaled by 1/16), Ks[256][64] (transposed),
//       Vs[64][256], Ps[64][65].  Online softmax in registers.
// Thread (ty,tx) of 16x16: score rows ty*4+{0..3}, score cols tx*4+{0..3};
// ctx cols = k2*32 + tx*2 (k2=0..7) -> conflict-free 128B V reads.
// ---------------------------------------------------------------------------
#define FLASH_SMEM ((16384 * 3 + 64 * 65) * 4)

__global__ __launch_bounds__(256, 1) void flash_attn(
    const float* __restrict__ q, const float* __restrict__ k,
    const float* __restrict__ v, float* __restrict__ o)
{
    extern __shared__ float sm[];
    float* Qs = sm;            // [256][64]
    float* Ks = sm + 16384;    // [256][64]
    float* Vs = sm + 32768;    // [64][256]
    float* Ps = sm + 49152;    // [64][65]

    const int tid = threadIdx.x;
    const int tx = tid & 15, ty = tid >> 4;
    const int b = blockIdx.x >> 6, qt = blockIdx.x & 63;
    const size_t qrow0 = (size_t)(b * 4096 + qt * 64);
    const float* qb = q + qrow0 * 256;
    const float scale = 0.0625f;  // 1/sqrt(256)

    // Load Q tile transposed, folding in the softmax scale.
#pragma unroll
    for (int i = 0; i < 16; i++) {
        int fi = tid + i * 256;
        int c = fi & 63, dq = fi >> 6;
        float4 av = *(const float4*)(qb + c * 256 + dq * 4);
        Qs[(dq * 4 + 0) * 64 + c] = av.x * scale;
        Qs[(dq * 4 + 1) * 64 + c] = av.y * scale;
        Qs[(dq * 4 + 2) * 64 + c] = av.z * scale;
        Qs[(dq * 4 + 3) * 64 + c] = av.w * scale;
    }

    float m_i[4] = {-1e30f, -1e30f, -1e30f, -1e30f};
    float l_i[4] = {0.f, 0.f, 0.f, 0.f};
    f2u ctxa[4][8] = {};   // [row][col pair], col = k2*32 + tx*2

    const float* kb0 = k + (size_t)b * 4096 * 256;
    const float* vb0 = v + (size_t)b * 4096 * 256;

    for (int kt = 0; kt < 64; kt++) {
        const float* kb = kb0 + kt * 64 * 256;
        const float* vb = vb0 + kt * 64 * 256;
        __syncthreads();   // smem reuse from previous PV
#pragma unroll
        for (int i = 0; i < 16; i++) {
            int fi = tid + i * 256;
            int c = fi & 63, dq = fi >> 6;
            float4 av = *(const float4*)(kb + c * 256 + dq * 4);
            Ks[(dq * 4 + 0) * 64 + c] = av.x;
            Ks[(dq * 4 + 1) * 64 + c] = av.y;
            Ks[(dq * 4 + 2) * 64 + c] = av.z;
            Ks[(dq * 4 + 3) * 64 + c] = av.w;
            *(float4*)&Vs[fi * 4] = *(const float4*)(vb + fi * 4);
        }
        __syncthreads();

        // --- scores: S = (Q/16) @ K^T, 4x4 per thread, f32x2 accumulate ---
        f2u sacc[4][2] = {};
#pragma unroll 8
        for (int d = 0; d < 256; d++) {
            float4 a = *(const float4*)&Qs[d * 64 + ty * 4];
            f2u k01 = *(const f2u*)&Ks[d * 64 + tx * 4];
            f2u k23 = *(const f2u*)&Ks[d * 64 + tx * 4 + 2];
            f2u t;
            t = dup2(a.x); ffma2(sacc[0][0], t, k01); ffma2(sacc[0][1], t, k23);
            t = dup2(a.y); ffma2(sacc[1][0], t, k01); ffma2(sacc[1][1], t, k23);
            t = dup2(a.z); ffma2(sacc[2][0], t, k01); ffma2(sacc[2][1], t, k23);
            t = dup2(a.w); ffma2(sacc[3][0], t, k01); ffma2(sacc[3][1], t, k23);
        }

        // --- online softmax update (row groups = 16 lanes sharing ty) ---
#pragma unroll
        for (int j = 0; j < 4; j++) {
            float s0, s1, s2, s3;
            upk2(s0, s1, sacc[j][0]); upk2(s2, s3, sacc[j][1]);
            float rmax = fmaxf(fmaxf(s0, s1), fmaxf(s2, s3));
#pragma unroll
            for (int msk = 1; msk < 16; msk <<= 1)
                rmax = fmaxf(rmax, __shfl_xor_sync(0xffffffffu, rmax, msk));
            float mnew = fmaxf(m_i[j], rmax);
            float alpha = __expf(m_i[j] - mnew);
            m_i[j] = mnew;
            float p0 = __expf(s0 - mnew), p1 = __expf(s1 - mnew);
            float p2 = __expf(s2 - mnew), p3 = __expf(s3 - mnew);
            int prow = (ty * 4 + j) * 65 + tx * 4;
            Ps[prow + 0] = p0; Ps[prow + 1] = p1;
            Ps[prow + 2] = p2; Ps[prow + 3] = p3;
            float rsum = p0 + p1 + p2 + p3;
#pragma unroll
            for (int msk = 1; msk < 16; msk <<= 1)
                rsum += __shfl_xor_sync(0xffffffffu, rsum, msk);
            l_i[j] = l_i[j] * alpha + rsum;
            f2u a2 = dup2(alpha);
#pragma unroll
            for (int k2 = 0; k2 < 8; k2++) fmul2(ctxa[j][k2], a2);
        }
        __syncthreads();   // Ps visible to all

        // --- PV: ctx += P @ V ---
#pragma unroll 2
        for (int jj = 0; jj < 64; jj++) {
            f2u pd0 = dup2(Ps[(ty * 4 + 0) * 65 + jj]);
            f2u pd1 = dup2(Ps[(ty * 4 + 1) * 65 + jj]);
            f2u pd2 = dup2(Ps[(ty * 4 + 2) * 65 + jj]);
            f2u pd3 = dup2(Ps[(ty * 4 + 3) * 65 + jj]);
#pragma unroll
            for (int k2 = 0; k2 < 8; k2++) {
                f2u vv = *(const f2u*)&Vs[jj * 256 + k2 * 32 + tx * 2];
                ffma2(ctxa[0][k2], pd0, vv);
                ffma2(ctxa[1][k2], pd1, vv);
                ffma2(ctxa[2][k2], pd2, vv);
                ffma2(ctxa[3][k2], pd3, vv);
            }
        }
    }

    // epilogue: ctx /= l, write out
#pragma unroll
    for (int j = 0; j < 4; j++) {
        float inv = 1.0f / l_i[j];
        float* orow = o + (qrow0 + ty * 4 + j) * 256;
#pragma unroll
        for (int k2 = 0; k2 < 8; k2++) {
            float x0, x1; upk2(x0, x1, ctxa[j][k2]);
            *(float2*)(orow + k2 * 32 + tx * 2) = make_float2(x0 * inv, x1 * inv);
        }
    }
}

// ---------------------------------------------------------------------------
// Pooling: w[row] = dot(logits[row,:], cv)  (one warp per row)
// ---------------------------------------------------------------------------
__global__ __launch_bounds__(256) void pool_w(
    const float* __restrict__ logits, const float* __restrict__ cv,
    float* __restrict__ w)
{
    int warp = threadIdx.x >> 5, lane = threadIdx.x & 31;
    int row = blockIdx.x * 8 + warp;
    const float* lr = logits + (size_t)row * 256;
    float s = 0.f;
#pragma unroll
    for (int i = 0; i < 8; i++) s += lr[i * 32 + lane] * cv[i * 32 + lane];
#pragma unroll
    for (int m = 16; m; m >>= 1) s += __shfl_xor_sync(0xffffffffu, s, m);
    if (lane == 0) w[row] = s;
}

// Softmax over the 4096 sequence positions of one batch (in place).
__global__ __launch_bounds__(256) void pool_softmax(float* __restrict__ w)
{
    __shared__ float red[8];
    int t = threadIdx.x;
    int warp = t >> 5, lane = t & 31;
    float* wb = w + blockIdx.x * 4096;
    float vals[16];
    float mx = -1e30f;
#pragma unroll
    for (int i = 0; i < 16; i++) { vals[i] = wb[t + i * 256]; mx = fmaxf(mx, vals[i]); }
#pragma unroll
    for (int m = 16; m; m >>= 1) mx = fmaxf(mx, __shfl_xor_sync(0xffffffffu, mx, m));
    if (lane == 0) red[warp] = mx;
    __syncthreads();
    float M = red[0];
#pragma unroll
    for (int i = 1; i < 8; i++) M = fmaxf(M, red[i]);
    __syncthreads();
    float s = 0.f;
#pragma unroll
    for (int i = 0; i < 16; i++) { vals[i] = __expf(vals[i] - M); s += vals[i]; }
#pragma unroll
    for (int m = 16; m; m >>= 1) s += __shfl_xor_sync(0xffffffffu, s, m);
    if (lane == 0) red[warp] = s;
    __syncthreads();
    float S = 0.f;
#pragma unroll
    for (int i = 0; i < 8; i++) S += red[i];
    float inv = 1.0f / S;
#pragma unroll
    for (int i = 0; i < 16; i++) wb[t + i * 256] = vals[i] * inv;
}

// out = logits * nw (broadcast over D). float4 per thread, covers all elements.
__global__ __launch_bounds__(256) void scale_out(
    const float* __restrict__ logits, const float* __restrict__ w,
    float* __restrict__ out)
{
    int i = blockIdx.x * 256 + threadIdx.x;   // float4 index; grid covers exactly
    float4 vv = *(const float4*)(logits + (size_t)i * 4);
    float nw = w[i >> 6];
    vv.x *= nw; vv.y *= nw; vv.z *= nw; vv.w *= nw;
    *(float4*)(out + (size_t)i * 4) = vv;
}

// ---------------------------------------------------------------------------
extern "C" void kernel_launch(void* const* d_in, const int* in_sizes, int n_in,
                              void* d_out, int out_size)
{
    const float* x  = (const float*)d_in[0];
    const float* Wq = (const float*)d_in[1];
    const float* bq = (const float*)d_in[2];
    const float* Wk = (const float*)d_in[3];
    const float* bk = (const float*)d_in[4];
    const float* Wv = (const float*)d_in[5];
    const float* bv = (const float*)d_in[6];
    const float* Wo = (const float*)d_in[7];
    const float* bo = (const float*)d_in[8];
    const float* cv = (const float*)d_in[9];
    float* out = (float*)d_out;

    float *gq, *gk, *gv, *gctx, *glog, *gw;
    cudaGetSymbolAddress((void**)&gq,   g_q);
    cudaGetSymbolAddress((void**)&gk,   g_k);
    cudaGetSymbolAddress((void**)&gv,   g_v);
    cudaGetSymbolAddress((void**)&gctx, g_ctx);
    cudaGetSymbolAddress((void**)&glog, g_logits);
    cudaGetSymbolAddress((void**)&gw,   g_w);

    cudaFuncSetAttribute(flash_attn, cudaFuncAttributeMaxDynamicSharedMemorySize,
                         FLASH_SMEM);

    dim3 gg(4, 512);
    sgemm_bias256<<<gg, 256>>>(x, Wq, bq, gq);
    sgemm_bias256<<<gg, 256>>>(x, Wk, bk, gk);
    sgemm_bias256<<<gg, 256>>>(x, Wv, bv, gv);
    flash_attn<<<512, 256, FLASH_SMEM>>>(gq, gk, gv, gctx);
    sgemm_bias256<<<gg, 256>>>(gctx, Wo, bo, glog);
    pool_w<<<4096, 256>>>(glog, cv, gw);
    pool_softmax<<<8, 256>>>(gw);
    scale_out<<<8192, 256>>>(glog, gw, out);
}